// round 3
// baseline (speedup 1.0000x reference)
#include <cuda_runtime.h>
#include <cuda_bf16.h>
#include <cstdint>

// Problem shape (fixed by the dataset): N=100000 nodes, 256 in-feats, 64 out-feats, E=3.2M edges.
#define NMAX   100000
#define KIN    256
#define COUT   64

// Scratch (no cudaMalloc allowed): degree array + transformed/pre-scaled features h' = (x@W)*rsqrt(deg).
__device__ float g_deg[NMAX];
__device__ float g_h[(size_t)NMAX * COUT];
__device__ int   g_idx64;   // 1 if edge_index is int64, 0 if int32

// ---------------------------------------------------------------------------
// 0) Detect edge_index dtype on-device (JAX may have demoted int64 -> int32).
//    int32 data reinterpreted as int64 gives values >= 2^32 almost surely.
// ---------------------------------------------------------------------------
__global__ void detect_idx_kernel(const long long* __restrict__ e64, int n_nodes) {
    __shared__ int bad;
    if (threadIdx.x == 0) bad = 0;
    __syncthreads();
    for (int i = threadIdx.x; i < 4096; i += blockDim.x) {
        long long v = e64[i];
        if (v < 0 || v >= (long long)n_nodes) atomicOr(&bad, 1);
    }
    __syncthreads();
    if (threadIdx.x == 0) g_idx64 = bad ? 0 : 1;
}

// ---------------------------------------------------------------------------
// 1) deg = 1 (self-loop) for all nodes
// ---------------------------------------------------------------------------
__global__ void init_deg_kernel(int n) {
    int i = blockIdx.x * blockDim.x + threadIdx.x;
    if (i < n) g_deg[i] = 1.0f;
}

// ---------------------------------------------------------------------------
// 2) deg[col[e]] += 1 for every edge
// ---------------------------------------------------------------------------
__global__ void deg_kernel(const void* __restrict__ ei, int E) {
    int e = blockIdx.x * blockDim.x + threadIdx.x;
    if (e >= E) return;
    int c;
    if (g_idx64) c = (int)((const long long*)ei)[(size_t)E + e];
    else         c = ((const int*)ei)[(size_t)E + e];
    atomicAdd(&g_deg[c], 1.0f);   // no return value -> RED
}

// ---------------------------------------------------------------------------
// 3) h' = (x @ W) * rsqrt(deg[row]).  Tile 128x64, TK=32, 256 threads,
//    4x8 register micro-tile per thread.
// ---------------------------------------------------------------------------
#define TM 128
#define TK 32
__global__ __launch_bounds__(256) void gemm_kernel(const float* __restrict__ x,
                                                   const float* __restrict__ W,
                                                   int n) {
    __shared__ float xs[TK][TM + 4];   // +4 floats pad: row stride 528 B (16B-aligned, conflict-free)
    __shared__ float ws[TK][COUT];

    const int t  = threadIdx.x;
    const int tx = t & 7;      // 8 column groups of 8
    const int ty = t >> 3;     // 32 row groups of 4
    const int row0 = blockIdx.x * TM;

    float acc[4][8];
#pragma unroll
    for (int i = 0; i < 4; i++)
#pragma unroll
        for (int j = 0; j < 8; j++) acc[i][j] = 0.0f;

#pragma unroll
    for (int k0 = 0; k0 < KIN; k0 += TK) {
        // load x tile: 128 rows x 32 k  (4 float4 per thread)
#pragma unroll
        for (int j = 0; j < 4; j++) {
            int i  = t + j * 256;        // 0..1023
            int r  = i >> 3;             // 0..127
            int kk = (i & 7) << 2;       // 0,4,...,28
            int gr = row0 + r;
            float4 v = make_float4(0.f, 0.f, 0.f, 0.f);
            if (gr < n) v = *(const float4*)(x + (size_t)gr * KIN + k0 + kk);
            xs[kk + 0][r] = v.x;
            xs[kk + 1][r] = v.y;
            xs[kk + 2][r] = v.z;
            xs[kk + 3][r] = v.w;
        }
        // load W tile: 32 x 64  (2 float4 per thread)
#pragma unroll
        for (int j = 0; j < 2; j++) {
            int i  = t + j * 256;        // 0..511
            int kk = i >> 4;             // 0..31
            int c  = (i & 15) << 2;      // 0..60
            *(float4*)&ws[kk][c] = *(const float4*)(W + (size_t)(k0 + kk) * COUT + c);
        }
        __syncthreads();

#pragma unroll
        for (int kk = 0; kk < TK; kk++) {
            float4 a  = *(float4*)&xs[kk][ty * 4];
            float4 w0 = *(float4*)&ws[kk][tx * 8];
            float4 w1 = *(float4*)&ws[kk][tx * 8 + 4];
            float av[4] = {a.x, a.y, a.z, a.w};
            float wv[8] = {w0.x, w0.y, w0.z, w0.w, w1.x, w1.y, w1.z, w1.w};
#pragma unroll
            for (int i = 0; i < 4; i++)
#pragma unroll
                for (int j = 0; j < 8; j++) acc[i][j] += av[i] * wv[j];
        }
        __syncthreads();
    }

    // epilogue: scale by rsqrt(deg[row]) and store h'
#pragma unroll
    for (int i = 0; i < 4; i++) {
        int gr = row0 + ty * 4 + i;
        if (gr < n) {
            float d = rsqrtf(g_deg[gr]);
            float4 o0 = make_float4(acc[i][0] * d, acc[i][1] * d, acc[i][2] * d, acc[i][3] * d);
            float4 o1 = make_float4(acc[i][4] * d, acc[i][5] * d, acc[i][6] * d, acc[i][7] * d);
            *(float4*)(g_h + (size_t)gr * COUT + tx * 8)     = o0;
            *(float4*)(g_h + (size_t)gr * COUT + tx * 8 + 4) = o1;
        }
    }
}

// ---------------------------------------------------------------------------
// 5) scatter: out[col] += h'[row].  16 threads per edge, float4 chunks,
//    vector reduction red.global.add.v4.f32 (sm_90+).
// ---------------------------------------------------------------------------
__global__ void scatter_kernel(const void* __restrict__ ei,
                               float* __restrict__ out, int E) {
    long long g = (long long)blockIdx.x * blockDim.x + threadIdx.x;
    if (g >= (long long)E * 16) return;
    int e = (int)(g >> 4);
    int q = (int)(g & 15);
    int r, c;
    if (g_idx64) {
        const long long* p = (const long long*)ei;
        r = (int)p[e];
        c = (int)p[(size_t)E + e];
    } else {
        const int* p = (const int*)ei;
        r = p[e];
        c = p[(size_t)E + e];
    }
    float4 v = *(const float4*)(g_h + (size_t)r * COUT + q * 4);
    float* dst = out + (size_t)c * COUT + q * 4;
    asm volatile("red.global.add.v4.f32 [%0], {%1, %2, %3, %4};"
                 :: "l"(dst), "f"(v.x), "f"(v.y), "f"(v.z), "f"(v.w)
                 : "memory");
}

// ---------------------------------------------------------------------------
// 6) finalize: out[i] = (out[i] + h'[i]) * rsqrt(deg[i]) + b
//    (self-loop contribution h'[i]*dinv[i] folded in here)
// ---------------------------------------------------------------------------
__global__ void finalize_kernel(float* __restrict__ out,
                                const float* __restrict__ b, int n) {
    int g = blockIdx.x * blockDim.x + threadIdx.x;
    if (g >= n * 16) return;
    int i = g >> 4;
    int q = (g & 15) * 4;
    float d = rsqrtf(g_deg[i]);
    float4 o = *(float4*)(out + (size_t)i * COUT + q);
    float4 h = *(const float4*)(g_h + (size_t)i * COUT + q);
    float4 bb = *(const float4*)(b + q);
    o.x = (o.x + h.x) * d + bb.x;
    o.y = (o.y + h.y) * d + bb.y;
    o.z = (o.z + h.z) * d + bb.z;
    o.w = (o.w + h.w) * d + bb.w;
    *(float4*)(out + (size_t)i * COUT + q) = o;
}

// ---------------------------------------------------------------------------
extern "C" void kernel_launch(void* const* d_in, const int* in_sizes, int n_in,
                              void* d_out, int out_size) {
    const float* x  = (const float*)d_in[0];
    const void*  ei = d_in[1];                 // int64 or int32, detected on device
    const float* W  = (const float*)d_in[2];
    const float* b  = (const float*)d_in[3];
    float* out = (float*)d_out;

    const int n = in_sizes[0] / KIN;           // 100000
    const int E = in_sizes[1] / 2;             // 3200000

    detect_idx_kernel<<<1, 256>>>((const long long*)ei, n);
    init_deg_kernel<<<(n + 255) / 256, 256>>>(n);
    deg_kernel<<<(E + 255) / 256, 256>>>(ei, E);
    gemm_kernel<<<(n + TM - 1) / TM, 256>>>(x, W, n);
    cudaMemsetAsync(d_out, 0, (size_t)n * COUT * sizeof(float));
    {
        long long total = (long long)E * 16;
        int blocks = (int)((total + 255) / 256);
        scatter_kernel<<<blocks, 256>>>(ei, out, E);
    }
    finalize_kernel<<<(n * 16 + 255) / 256, 256>>>(out, b, n);
}

// round 6
// speedup vs baseline: 1.2790x; 1.2790x over previous
#include <cuda_runtime.h>
#include <cuda_bf16.h>
#include <cstdint>

// Problem shape (fixed by the dataset): N=100000 nodes, 256 in-feats, 64 out-feats, E=3.2M edges.
#define NMAX   100000
#define EMAX   3200000
#define KIN    256
#define COUT   64
#define NBLK   ((NMAX + 255) / 256)   // 391

// Scratch (no cudaMalloc allowed).
__device__ float g_h[(size_t)NMAX * COUT];   // h' = (x@W) * rsqrt(deg)
__device__ int   g_degi[NMAX];               // incoming-edge count (excl. self-loop)
__device__ int   g_off[NMAX];                // CSR offsets (exclusive scan of degi)
__device__ int   g_cur[NMAX];                // fill cursors
__device__ int   g_srcl[EMAX];               // CSR: source node per incoming edge
__device__ int   g_bsum[NBLK];
__device__ int   g_bbase[NBLK];
__device__ int   g_idx64;                    // 1 if edge_index is int64, 0 if int32

// ---------------------------------------------------------------------------
// 0) Detect edge_index dtype on-device (JAX may have demoted int64 -> int32).
// ---------------------------------------------------------------------------
__global__ void detect_idx_kernel(const long long* __restrict__ e64, int n_nodes) {
    __shared__ int bad;
    if (threadIdx.x == 0) bad = 0;
    __syncthreads();
    for (int i = threadIdx.x; i < 4096; i += blockDim.x) {
        long long v = e64[i];
        if (v < 0 || v >= (long long)n_nodes) atomicOr(&bad, 1);
    }
    __syncthreads();
    if (threadIdx.x == 0) g_idx64 = bad ? 0 : 1;
}

__device__ __forceinline__ void load_edge(const void* ei, int E, int e, int& r, int& c) {
    if (g_idx64) {
        const long long* p = (const long long*)ei;
        r = (int)__ldg(&p[e]);
        c = (int)__ldg(&p[(size_t)E + e]);
    } else {
        const int* p = (const int*)ei;
        r = __ldg(&p[e]);
        c = __ldg(&p[(size_t)E + e]);
    }
}

// ---------------------------------------------------------------------------
// 1) degi = 0
// ---------------------------------------------------------------------------
__global__ void zero_deg_kernel(int n) {
    int i = blockIdx.x * blockDim.x + threadIdx.x;
    if (i < n) g_degi[i] = 0;
}

// ---------------------------------------------------------------------------
// 2) degi[col[e]] += 1
// ---------------------------------------------------------------------------
__global__ void count_kernel(const void* __restrict__ ei, int E) {
    int e = blockIdx.x * blockDim.x + threadIdx.x;
    if (e >= E) return;
    int r, c;
    load_edge(ei, E, e, r, c);
    atomicAdd(&g_degi[c], 1);
}

// ---------------------------------------------------------------------------
// 3) two-level exclusive scan of degi -> off, cur
// ---------------------------------------------------------------------------
__global__ void scanA_kernel(int n) {
    __shared__ int s[256];
    int i = blockIdx.x * 256 + threadIdx.x;
    int v = (i < n) ? g_degi[i] : 0;
    s[threadIdx.x] = v;
    __syncthreads();
#pragma unroll
    for (int off = 1; off < 256; off <<= 1) {
        int t = (threadIdx.x >= off) ? s[threadIdx.x - off] : 0;
        __syncthreads();
        s[threadIdx.x] += t;
        __syncthreads();
    }
    if (i < n) g_off[i] = s[threadIdx.x] - v;          // exclusive
    if (threadIdx.x == 255) g_bsum[blockIdx.x] = s[255];
}

__global__ void scanB_kernel(int nb) {
    __shared__ int s[512];
    int v = (threadIdx.x < nb) ? g_bsum[threadIdx.x] : 0;
    s[threadIdx.x] = v;
    __syncthreads();
#pragma unroll
    for (int off = 1; off < 512; off <<= 1) {
        int t = (threadIdx.x >= off) ? s[threadIdx.x - off] : 0;
        __syncthreads();
        s[threadIdx.x] += t;
        __syncthreads();
    }
    if (threadIdx.x < nb) g_bbase[threadIdx.x] = s[threadIdx.x] - v;
}

__global__ void scanC_kernel(int n) {
    int i = blockIdx.x * 256 + threadIdx.x;
    if (i < n) {
        int o = g_off[i] + g_bbase[blockIdx.x];
        g_off[i] = o;
        g_cur[i] = o;
    }
}

// ---------------------------------------------------------------------------
// 4) fill CSR: g_srcl[cur[c]++] = r
// ---------------------------------------------------------------------------
__global__ void fill_kernel(const void* __restrict__ ei, int E) {
    int e = blockIdx.x * blockDim.x + threadIdx.x;
    if (e >= E) return;
    int r, c;
    load_edge(ei, E, e, r, c);
    int pos = atomicAdd(&g_cur[c], 1);
    g_srcl[pos] = r;
}

// ---------------------------------------------------------------------------
// 5) h' = (x @ W) * rsqrt(degi+1).  Tile 128x64, TK=32, 128 threads,
//    8x8 register micro-tile per thread (4 LDS.128 per 64 FFMA).
// ---------------------------------------------------------------------------
#define TM 128
#define TK 32
__global__ __launch_bounds__(128) void gemm_kernel(const float* __restrict__ x,
                                                   const float* __restrict__ W,
                                                   int n) {
    __shared__ float xs[TK][TM + 4];   // transposed x tile, padded
    __shared__ float ws[TK][COUT];

    const int t  = threadIdx.x;
    const int tx = t & 7;      // 8 column groups of 8
    const int ty = t >> 3;     // 16 row groups of 8
    const int row0 = blockIdx.x * TM;

    float acc[8][8];
#pragma unroll
    for (int i = 0; i < 8; i++)
#pragma unroll
        for (int j = 0; j < 8; j++) acc[i][j] = 0.0f;

#pragma unroll
    for (int k0 = 0; k0 < KIN; k0 += TK) {
#pragma unroll
        for (int j = 0; j < 8; j++) {
            int i  = t + j * 128;        // 0..1023
            int r  = i >> 3;             // 0..127
            int kk = (i & 7) << 2;       // 0,4,...,28
            int gr = row0 + r;
            float4 v = make_float4(0.f, 0.f, 0.f, 0.f);
            if (gr < n) v = *(const float4*)(x + (size_t)gr * KIN + k0 + kk);
            xs[kk + 0][r] = v.x;
            xs[kk + 1][r] = v.y;
            xs[kk + 2][r] = v.z;
            xs[kk + 3][r] = v.w;
        }
#pragma unroll
        for (int j = 0; j < 4; j++) {
            int i  = t + j * 128;        // 0..511
            int kk = i >> 4;             // 0..31
            int c  = (i & 15) << 2;      // 0..60
            *(float4*)&ws[kk][c] = *(const float4*)(W + (size_t)(k0 + kk) * COUT + c);
        }
        __syncthreads();

#pragma unroll
        for (int kk = 0; kk < TK; kk++) {
            float av[8], wv[8];
            *(float4*)&av[0] = *(float4*)&xs[kk][ty * 8];
            *(float4*)&av[4] = *(float4*)&xs[kk][ty * 8 + 4];
            *(float4*)&wv[0] = *(float4*)&ws[kk][tx * 8];
            *(float4*)&wv[4] = *(float4*)&ws[kk][tx * 8 + 4];
#pragma unroll
            for (int i = 0; i < 8; i++)
#pragma unroll
                for (int j = 0; j < 8; j++) acc[i][j] += av[i] * wv[j];
        }
        __syncthreads();
    }

#pragma unroll
    for (int i = 0; i < 8; i++) {
        int gr = row0 + ty * 8 + i;
        if (gr < n) {
            float d = rsqrtf((float)g_degi[gr] + 1.0f);
            float4 o0 = make_float4(acc[i][0] * d, acc[i][1] * d, acc[i][2] * d, acc[i][3] * d);
            float4 o1 = make_float4(acc[i][4] * d, acc[i][5] * d, acc[i][6] * d, acc[i][7] * d);
            *(float4*)(g_h + (size_t)gr * COUT + tx * 8)     = o0;
            *(float4*)(g_h + (size_t)gr * COUT + tx * 8 + 4) = o1;
        }
    }
}

// ---------------------------------------------------------------------------
// 6) gather + finalize: one warp per node.
//    out[i] = (sum_{s in in(i)} h'[s] + h'[i]) * rsqrt(deg) + b
//    Each lane owns 2 output columns (float2). Index loads amortized via shfl.
// ---------------------------------------------------------------------------
__global__ __launch_bounds__(256) void gather_kernel(const float* __restrict__ b,
                                                     float* __restrict__ out, int n) {
    int warp = (blockIdx.x * 256 + threadIdx.x) >> 5;
    int lane = threadIdx.x & 31;
    if (warp >= n) return;

    const int beg = g_off[warp];
    const int d   = g_degi[warp];

    float2 acc0 = make_float2(0.f, 0.f);
    float2 acc1 = make_float2(0.f, 0.f);

    for (int j0 = 0; j0 < d; j0 += 32) {
        int sl = (j0 + lane < d) ? g_srcl[beg + j0 + lane] : 0;
        int m  = min(32, d - j0);
        int j  = 0;
        for (; j + 1 < m; j += 2) {
            int s0 = __shfl_sync(0xffffffffu, sl, j);
            int s1 = __shfl_sync(0xffffffffu, sl, j + 1);
            float2 v0 = *(const float2*)(g_h + (size_t)s0 * COUT + lane * 2);
            float2 v1 = *(const float2*)(g_h + (size_t)s1 * COUT + lane * 2);
            acc0.x += v0.x; acc0.y += v0.y;
            acc1.x += v1.x; acc1.y += v1.y;
        }
        if (j < m) {
            int s0 = __shfl_sync(0xffffffffu, sl, j);
            float2 v0 = *(const float2*)(g_h + (size_t)s0 * COUT + lane * 2);
            acc0.x += v0.x; acc0.y += v0.y;
        }
    }

    // self-loop + normalize + bias
    float2 hs = *(const float2*)(g_h + (size_t)warp * COUT + lane * 2);
    float dinv = rsqrtf((float)d + 1.0f);
    float2 bb = *(const float2*)(b + lane * 2);
    float2 o;
    o.x = (acc0.x + acc1.x + hs.x) * dinv + bb.x;
    o.y = (acc0.y + acc1.y + hs.y) * dinv + bb.y;
    *(float2*)(out + (size_t)warp * COUT + lane * 2) = o;
}

// ---------------------------------------------------------------------------
extern "C" void kernel_launch(void* const* d_in, const int* in_sizes, int n_in,
                              void* d_out, int out_size) {
    const float* x  = (const float*)d_in[0];
    const void*  ei = d_in[1];                 // int64 or int32, detected on device
    const float* W  = (const float*)d_in[2];
    const float* b  = (const float*)d_in[3];
    float* out = (float*)d_out;

    const int n = in_sizes[0] / KIN;           // 100000
    const int E = in_sizes[1] / 2;             // 3200000
    const int nblk = (n + 255) / 256;

    detect_idx_kernel<<<1, 256>>>((const long long*)ei, n);
    zero_deg_kernel<<<nblk, 256>>>(n);
    count_kernel<<<(E + 255) / 256, 256>>>(ei, E);
    scanA_kernel<<<nblk, 256>>>(n);
    scanB_kernel<<<1, 512>>>(nblk);
    scanC_kernel<<<nblk, 256>>>(n);
    fill_kernel<<<(E + 255) / 256, 256>>>(ei, E);
    gemm_kernel<<<(n + TM - 1) / TM, 128>>>(x, W, n);
    gather_kernel<<<(n * 32 + 255) / 256, 256>>>(b, out, n);
}

// round 7
// speedup vs baseline: 1.7456x; 1.3648x over previous
#include <cuda_runtime.h>
#include <cuda_bf16.h>
#include <cstdint>

// Problem shape (fixed by the dataset): N=100000 nodes, 256 in-feats, 64 out-feats, E=3.2M edges.
#define NMAX   100000
#define EMAX   3200000
#define KIN    256
#define COUT   64
#define NBLK   ((NMAX + 255) / 256)   // 391

// Scratch (no cudaMalloc allowed).
__device__ float g_h[(size_t)NMAX * COUT];   // h' = (x@W) * rsqrt(deg)
__device__ int   g_degi[NMAX];               // incoming-edge count (excl. self-loop)
__device__ int   g_off[NMAX];                // CSR offsets (exclusive scan of degi)
__device__ int   g_cur[NMAX];                // fill cursors
__device__ int   g_srcl[EMAX];               // CSR: source node per incoming edge
__device__ int   g_bsum[NBLK];
__device__ int   g_bbase[NBLK];
__device__ int   g_idx64;                    // 1 if edge_index is int64, 0 if int32

// ---------------------------------------------------------------------------
// 0) Detect edge_index dtype on-device (JAX may have demoted int64 -> int32).
// ---------------------------------------------------------------------------
__global__ void detect_idx_kernel(const long long* __restrict__ e64, int n_nodes) {
    __shared__ int bad;
    if (threadIdx.x == 0) bad = 0;
    __syncthreads();
    for (int i = threadIdx.x; i < 4096; i += blockDim.x) {
        long long v = e64[i];
        if (v < 0 || v >= (long long)n_nodes) atomicOr(&bad, 1);
    }
    __syncthreads();
    if (threadIdx.x == 0) g_idx64 = bad ? 0 : 1;
}

__device__ __forceinline__ void load_edge(const void* ei, int E, int e, int& r, int& c) {
    if (g_idx64) {
        const long long* p = (const long long*)ei;
        r = (int)__ldg(&p[e]);
        c = (int)__ldg(&p[(size_t)E + e]);
    } else {
        const int* p = (const int*)ei;
        r = __ldg(&p[e]);
        c = __ldg(&p[(size_t)E + e]);
    }
}

// ---------------------------------------------------------------------------
// 1) degi = 0
// ---------------------------------------------------------------------------
__global__ void zero_deg_kernel(int n) {
    int i = blockIdx.x * blockDim.x + threadIdx.x;
    if (i < n) g_degi[i] = 0;
}

// ---------------------------------------------------------------------------
// 2) degi[col[e]] += 1
// ---------------------------------------------------------------------------
__global__ void count_kernel(const void* __restrict__ ei, int E) {
    int e = blockIdx.x * blockDim.x + threadIdx.x;
    if (e >= E) return;
    int r, c;
    load_edge(ei, E, e, r, c);
    atomicAdd(&g_degi[c], 1);
}

// ---------------------------------------------------------------------------
// 3) two-level exclusive scan of degi -> off, cur
// ---------------------------------------------------------------------------
__global__ void scanA_kernel(int n) {
    __shared__ int s[256];
    int i = blockIdx.x * 256 + threadIdx.x;
    int v = (i < n) ? g_degi[i] : 0;
    s[threadIdx.x] = v;
    __syncthreads();
#pragma unroll
    for (int off = 1; off < 256; off <<= 1) {
        int t = (threadIdx.x >= off) ? s[threadIdx.x - off] : 0;
        __syncthreads();
        s[threadIdx.x] += t;
        __syncthreads();
    }
    if (i < n) g_off[i] = s[threadIdx.x] - v;          // exclusive
    if (threadIdx.x == 255) g_bsum[blockIdx.x] = s[255];
}

__global__ void scanB_kernel(int nb) {
    __shared__ int s[512];
    int v = (threadIdx.x < nb) ? g_bsum[threadIdx.x] : 0;
    s[threadIdx.x] = v;
    __syncthreads();
#pragma unroll
    for (int off = 1; off < 512; off <<= 1) {
        int t = (threadIdx.x >= off) ? s[threadIdx.x - off] : 0;
        __syncthreads();
        s[threadIdx.x] += t;
        __syncthreads();
    }
    if (threadIdx.x < nb) g_bbase[threadIdx.x] = s[threadIdx.x] - v;
}

__global__ void scanC_kernel(int n) {
    int i = blockIdx.x * 256 + threadIdx.x;
    if (i < n) {
        int o = g_off[i] + g_bbase[blockIdx.x];
        g_off[i] = o;
        g_cur[i] = o;
    }
}

// ---------------------------------------------------------------------------
// 4) fill CSR: g_srcl[cur[c]++] = r
// ---------------------------------------------------------------------------
__global__ void fill_kernel(const void* __restrict__ ei, int E) {
    int e = blockIdx.x * blockDim.x + threadIdx.x;
    if (e >= E) return;
    int r, c;
    load_edge(ei, E, e, r, c);
    int pos = atomicAdd(&g_cur[c], 1);
    g_srcl[pos] = r;
}

// ---------------------------------------------------------------------------
// 5) h' = (x @ W) * rsqrt(degi+1) via 3xTF32 tensor-core MMA.
//    Block: 256 threads = 8 warps; tile 128 rows x 64 cols; warp w owns rows
//    w*16..w*16+15.  K chunk = 16 (2 mma K-steps of 8).
//    SMEM strides: A tile stride 20, W tile stride 72 -> both fragment read
//    patterns touch 32 distinct banks (conflict-free).
//    3xTF32: v = hi + lo (both tf32-rounded); D += Ah*Bh + Al*Bh + Ah*Bl.
// ---------------------------------------------------------------------------
#define TM 128
#define TKC 16

__device__ __forceinline__ void split_tf32(float v, float& hi, float& lo) {
    uint32_t u;
    asm("cvt.rna.tf32.f32 %0, %1;" : "=r"(u) : "f"(v));
    hi = __uint_as_float(u);
    float l = v - hi;
    asm("cvt.rna.tf32.f32 %0, %1;" : "=r"(u) : "f"(l));
    lo = __uint_as_float(u);
}

__device__ __forceinline__ void mma_tf32(float* c, const uint32_t* a,
                                         uint32_t b0, uint32_t b1) {
    asm volatile("mma.sync.aligned.m16n8k8.row.col.f32.tf32.tf32.f32 "
                 "{%0,%1,%2,%3}, {%4,%5,%6,%7}, {%8,%9}, {%0,%1,%2,%3};"
                 : "+f"(c[0]), "+f"(c[1]), "+f"(c[2]), "+f"(c[3])
                 : "r"(a[0]), "r"(a[1]), "r"(a[2]), "r"(a[3]),
                   "r"(b0), "r"(b1));
}

__global__ __launch_bounds__(256) void gemm_kernel(const float* __restrict__ x,
                                                   const float* __restrict__ W,
                                                   int n) {
    __shared__ float xs_h[TM][20];    // stride 20: frag reads conflict-free
    __shared__ float xs_l[TM][20];
    __shared__ float ws_h[TKC][72];   // stride 72 (== 8 mod 32): conflict-free
    __shared__ float ws_l[TKC][72];

    const int t    = threadIdx.x;
    const int warp = t >> 5;
    const int lane = t & 31;
    const int lq   = lane >> 2;   // groupID 0..7
    const int kc   = lane & 3;    // threadID_in_group 0..3
    const int wrow = warp * 16;
    const int row0 = blockIdx.x * TM;

    float acc[8][4];
#pragma unroll
    for (int i = 0; i < 8; i++)
#pragma unroll
        for (int j = 0; j < 4; j++) acc[i][j] = 0.0f;

#pragma unroll
    for (int k0 = 0; k0 < KIN; k0 += TKC) {
        // load x tile: 128 rows x 16 k = 512 float4, 2 per thread, split hi/lo
#pragma unroll
        for (int j = 0; j < 2; j++) {
            int i  = t + j * 256;        // 0..511
            int r  = i >> 2;             // 0..127
            int kq = (i & 3) << 2;       // 0,4,8,12
            int gr = row0 + r;
            float4 v = make_float4(0.f, 0.f, 0.f, 0.f);
            if (gr < n) v = *(const float4*)(x + (size_t)gr * KIN + k0 + kq);
            float4 h4, l4;
            split_tf32(v.x, h4.x, l4.x);
            split_tf32(v.y, h4.y, l4.y);
            split_tf32(v.z, h4.z, l4.z);
            split_tf32(v.w, h4.w, l4.w);
            *(float4*)&xs_h[r][kq] = h4;
            *(float4*)&xs_l[r][kq] = l4;
        }
        // load W tile: 16 x 64 = 256 float4, 1 per thread, split hi/lo
        {
            int kk = t >> 4;             // 0..15
            int c  = (t & 15) << 2;      // 0..60
            float4 v = *(const float4*)(W + (size_t)(k0 + kk) * COUT + c);
            float4 h4, l4;
            split_tf32(v.x, h4.x, l4.x);
            split_tf32(v.y, h4.y, l4.y);
            split_tf32(v.z, h4.z, l4.z);
            split_tf32(v.w, h4.w, l4.w);
            *(float4*)&ws_h[kk][c] = h4;
            *(float4*)&ws_l[kk][c] = l4;
        }
        __syncthreads();

#pragma unroll
        for (int kk = 0; kk < TKC; kk += 8) {
            uint32_t ah[4], al[4];
            const int rA = wrow + lq;
            ah[0] = __float_as_uint(xs_h[rA][kk + kc]);
            ah[1] = __float_as_uint(xs_h[rA + 8][kk + kc]);
            ah[2] = __float_as_uint(xs_h[rA][kk + kc + 4]);
            ah[3] = __float_as_uint(xs_h[rA + 8][kk + kc + 4]);
            al[0] = __float_as_uint(xs_l[rA][kk + kc]);
            al[1] = __float_as_uint(xs_l[rA + 8][kk + kc]);
            al[2] = __float_as_uint(xs_l[rA][kk + kc + 4]);
            al[3] = __float_as_uint(xs_l[rA + 8][kk + kc + 4]);
#pragma unroll
            for (int nt = 0; nt < 8; nt++) {
                int col = nt * 8 + lq;
                uint32_t bh0 = __float_as_uint(ws_h[kk + kc][col]);
                uint32_t bh1 = __float_as_uint(ws_h[kk + kc + 4][col]);
                uint32_t bl0 = __float_as_uint(ws_l[kk + kc][col]);
                uint32_t bl1 = __float_as_uint(ws_l[kk + kc + 4][col]);
                mma_tf32(acc[nt], ah, bh0, bh1);   // hi*hi
                mma_tf32(acc[nt], al, bh0, bh1);   // lo*hi
                mma_tf32(acc[nt], ah, bl0, bl1);   // hi*lo
            }
        }
        __syncthreads();
    }

    // epilogue: scale by rsqrt(deg) and store h'
    // c0 -> (row lq,   col 2kc), c1 -> col 2kc+1, c2/c3 -> row lq+8
    const int gr0 = row0 + wrow + lq;
    const int gr1 = gr0 + 8;
    float d0 = (gr0 < n) ? rsqrtf((float)g_degi[gr0] + 1.0f) : 0.f;
    float d1 = (gr1 < n) ? rsqrtf((float)g_degi[gr1] + 1.0f) : 0.f;
#pragma unroll
    for (int nt = 0; nt < 8; nt++) {
        int col = nt * 8 + kc * 2;
        if (gr0 < n) {
            float2 o = make_float2(acc[nt][0] * d0, acc[nt][1] * d0);
            *(float2*)(g_h + (size_t)gr0 * COUT + col) = o;
        }
        if (gr1 < n) {
            float2 o = make_float2(acc[nt][2] * d1, acc[nt][3] * d1);
            *(float2*)(g_h + (size_t)gr1 * COUT + col) = o;
        }
    }
}

// ---------------------------------------------------------------------------
// 6) gather + finalize: one warp per node.
//    out[i] = (sum_{s in in(i)} h'[s] + h'[i]) * rsqrt(deg) + b
// ---------------------------------------------------------------------------
__global__ __launch_bounds__(256) void gather_kernel(const float* __restrict__ b,
                                                     float* __restrict__ out, int n) {
    int warp = (blockIdx.x * 256 + threadIdx.x) >> 5;
    int lane = threadIdx.x & 31;
    if (warp >= n) return;

    const int beg = g_off[warp];
    const int d   = g_degi[warp];

    float2 acc0 = make_float2(0.f, 0.f);
    float2 acc1 = make_float2(0.f, 0.f);

    for (int j0 = 0; j0 < d; j0 += 32) {
        int sl = (j0 + lane < d) ? g_srcl[beg + j0 + lane] : 0;
        int m  = min(32, d - j0);
        int j  = 0;
        for (; j + 1 < m; j += 2) {
            int s0 = __shfl_sync(0xffffffffu, sl, j);
            int s1 = __shfl_sync(0xffffffffu, sl, j + 1);
            float2 v0 = *(const float2*)(g_h + (size_t)s0 * COUT + lane * 2);
            float2 v1 = *(const float2*)(g_h + (size_t)s1 * COUT + lane * 2);
            acc0.x += v0.x; acc0.y += v0.y;
            acc1.x += v1.x; acc1.y += v1.y;
        }
        if (j < m) {
            int s0 = __shfl_sync(0xffffffffu, sl, j);
            float2 v0 = *(const float2*)(g_h + (size_t)s0 * COUT + lane * 2);
            acc0.x += v0.x; acc0.y += v0.y;
        }
    }

    // self-loop + normalize + bias
    float2 hs = *(const float2*)(g_h + (size_t)warp * COUT + lane * 2);
    float dinv = rsqrtf((float)d + 1.0f);
    float2 bb = *(const float2*)(b + lane * 2);
    float2 o;
    o.x = (acc0.x + acc1.x + hs.x) * dinv + bb.x;
    o.y = (acc0.y + acc1.y + hs.y) * dinv + bb.y;
    *(float2*)(out + (size_t)warp * COUT + lane * 2) = o;
}

// ---------------------------------------------------------------------------
extern "C" void kernel_launch(void* const* d_in, const int* in_sizes, int n_in,
                              void* d_out, int out_size) {
    const float* x  = (const float*)d_in[0];
    const void*  ei = d_in[1];                 // int64 or int32, detected on device
    const float* W  = (const float*)d_in[2];
    const float* b  = (const float*)d_in[3];
    float* out = (float*)d_out;

    const int n = in_sizes[0] / KIN;           // 100000
    const int E = in_sizes[1] / 2;             // 3200000
    const int nblk = (n + 255) / 256;

    detect_idx_kernel<<<1, 256>>>((const long long*)ei, n);
    zero_deg_kernel<<<nblk, 256>>>(n);
    count_kernel<<<(E + 255) / 256, 256>>>(ei, E);
    scanA_kernel<<<nblk, 256>>>(n);
    scanB_kernel<<<1, 512>>>(nblk);
    scanC_kernel<<<nblk, 256>>>(n);
    fill_kernel<<<(E + 255) / 256, 256>>>(ei, E);
    gemm_kernel<<<(n + TM - 1) / TM, 256>>>(x, W, n);
    gather_kernel<<<(n * 32 + 255) / 256, 256>>>(b, out, n);
}

// round 8
// speedup vs baseline: 1.9871x; 1.1383x over previous
#include <cuda_runtime.h>
#include <cuda_bf16.h>
#include <cstdint>

// Problem shape (fixed by the dataset): N=100000 nodes, 256 in-feats, 64 out-feats, E=3.2M edges.
#define NMAX   100000
#define EMAX   3200000
#define KIN    256
#define COUT   64
#define NBLK   ((NMAX + 255) / 256)   // 391
#define TM     128
#define TKC    16
#define GEMM_BLOCKS ((NMAX + TM - 1) / TM)   // 782

// Scratch (no cudaMalloc allowed).
__device__ float g_h[(size_t)NMAX * COUT];   // h = x@W, then normalized in-place to h' = h*dinv
__device__ float g_dinv[NMAX];               // rsqrt(deg+1)
__device__ int   g_degi[NMAX];               // incoming-edge count (excl. self-loop)
__device__ int   g_off[NMAX];                // CSR offsets (exclusive scan of degi)
__device__ int   g_cur[NMAX];                // fill cursors
__device__ int   g_srcl[EMAX];               // CSR: source node per incoming edge
__device__ int   g_bsum[NBLK];
__device__ int   g_bbase[NBLK];
__device__ int   g_idx64;                    // 1 if edge_index is int64, 0 if int32

// ---------------------------------------------------------------------------
// helpers
// ---------------------------------------------------------------------------
__device__ __forceinline__ int load_col(const void* ei, int E, int e) {
    if (g_idx64) return (int)__ldg(&((const long long*)ei)[(size_t)E + e]);
    return __ldg(&((const int*)ei)[(size_t)E + e]);
}
__device__ __forceinline__ int load_row(const void* ei, int e) {
    if (g_idx64) return (int)__ldg(&((const long long*)ei)[e]);
    return __ldg(&((const int*)ei)[e]);
}

__device__ __forceinline__ void split_tf32(float v, float& hi, float& lo) {
    uint32_t u;
    asm("cvt.rna.tf32.f32 %0, %1;" : "=r"(u) : "f"(v));
    hi = __uint_as_float(u);
    float l = v - hi;
    asm("cvt.rna.tf32.f32 %0, %1;" : "=r"(u) : "f"(l));
    lo = __uint_as_float(u);
}

__device__ __forceinline__ void mma_tf32(float* c, const uint32_t* a,
                                         uint32_t b0, uint32_t b1) {
    asm volatile("mma.sync.aligned.m16n8k8.row.col.f32.tf32.tf32.f32 "
                 "{%0,%1,%2,%3}, {%4,%5,%6,%7}, {%8,%9}, {%0,%1,%2,%3};"
                 : "+f"(c[0]), "+f"(c[1]), "+f"(c[2]), "+f"(c[3])
                 : "r"(a[0]), "r"(a[1]), "r"(a[2]), "r"(a[3]),
                   "r"(b0), "r"(b1));
}

// ---------------------------------------------------------------------------
// 1) detect dtype (block 0) + zero degi (blocks 1..NBLK)
// ---------------------------------------------------------------------------
__global__ void detect_zero_kernel(const long long* __restrict__ e64, int n) {
    if (blockIdx.x == 0) {
        __shared__ int bad;
        if (threadIdx.x == 0) bad = 0;
        __syncthreads();
        for (int i = threadIdx.x; i < 4096; i += blockDim.x) {
            long long v = e64[i];
            if (v < 0 || v >= (long long)n) atomicOr(&bad, 1);
        }
        __syncthreads();
        if (threadIdx.x == 0) g_idx64 = bad ? 0 : 1;
    } else {
        int i = (blockIdx.x - 1) * 256 + threadIdx.x;
        if (i < n) g_degi[i] = 0;
    }
}

// ---------------------------------------------------------------------------
// 2) FUSED: gemm (blocks [0,GEMM_BLOCKS)) + degree count (remaining blocks).
//    gemm: h = x @ W (UNNORMALIZED) via 3xTF32 MMA, 128x64 tile, 8 warps.
//    count: 4 edges/thread, atomicAdd on g_degi[col].
// ---------------------------------------------------------------------------
__global__ __launch_bounds__(256) void gemm_count_kernel(const float* __restrict__ x,
                                                         const float* __restrict__ W,
                                                         const void* __restrict__ ei,
                                                         int n, int E) {
    __shared__ float xs_h[TM][20];    // stride 20: frag reads conflict-free
    __shared__ float xs_l[TM][20];
    __shared__ float ws_h[TKC][72];   // stride 72 (== 8 mod 32): conflict-free
    __shared__ float ws_l[TKC][72];

    if (blockIdx.x >= GEMM_BLOCKS) {
        // ---- count role ----
        int e0 = ((blockIdx.x - GEMM_BLOCKS) * 256 + threadIdx.x) * 4;
#pragma unroll
        for (int k = 0; k < 4; k++) {
            int e = e0 + k;
            if (e < E) atomicAdd(&g_degi[load_col(ei, E, e)], 1);
        }
        return;
    }

    // ---- gemm role ----
    const int t    = threadIdx.x;
    const int warp = t >> 5;
    const int lane = t & 31;
    const int lq   = lane >> 2;   // groupID 0..7
    const int kc   = lane & 3;    // threadID_in_group 0..3
    const int wrow = warp * 16;
    const int row0 = blockIdx.x * TM;

    float acc[8][4];
#pragma unroll
    for (int i = 0; i < 8; i++)
#pragma unroll
        for (int j = 0; j < 4; j++) acc[i][j] = 0.0f;

#pragma unroll
    for (int k0 = 0; k0 < KIN; k0 += TKC) {
#pragma unroll
        for (int j = 0; j < 2; j++) {
            int i  = t + j * 256;        // 0..511
            int r  = i >> 2;             // 0..127
            int kq = (i & 3) << 2;       // 0,4,8,12
            int gr = row0 + r;
            float4 v = make_float4(0.f, 0.f, 0.f, 0.f);
            if (gr < n) v = *(const float4*)(x + (size_t)gr * KIN + k0 + kq);
            float4 h4, l4;
            split_tf32(v.x, h4.x, l4.x);
            split_tf32(v.y, h4.y, l4.y);
            split_tf32(v.z, h4.z, l4.z);
            split_tf32(v.w, h4.w, l4.w);
            *(float4*)&xs_h[r][kq] = h4;
            *(float4*)&xs_l[r][kq] = l4;
        }
        {
            int kk = t >> 4;             // 0..15
            int c  = (t & 15) << 2;      // 0..60
            float4 v = *(const float4*)(W + (size_t)(k0 + kk) * COUT + c);
            float4 h4, l4;
            split_tf32(v.x, h4.x, l4.x);
            split_tf32(v.y, h4.y, l4.y);
            split_tf32(v.z, h4.z, l4.z);
            split_tf32(v.w, h4.w, l4.w);
            *(float4*)&ws_h[kk][c] = h4;
            *(float4*)&ws_l[kk][c] = l4;
        }
        __syncthreads();

#pragma unroll
        for (int kk = 0; kk < TKC; kk += 8) {
            uint32_t ah[4], al[4];
            const int rA = wrow + lq;
            ah[0] = __float_as_uint(xs_h[rA][kk + kc]);
            ah[1] = __float_as_uint(xs_h[rA + 8][kk + kc]);
            ah[2] = __float_as_uint(xs_h[rA][kk + kc + 4]);
            ah[3] = __float_as_uint(xs_h[rA + 8][kk + kc + 4]);
            al[0] = __float_as_uint(xs_l[rA][kk + kc]);
            al[1] = __float_as_uint(xs_l[rA + 8][kk + kc]);
            al[2] = __float_as_uint(xs_l[rA][kk + kc + 4]);
            al[3] = __float_as_uint(xs_l[rA + 8][kk + kc + 4]);
#pragma unroll
            for (int nt = 0; nt < 8; nt++) {
                int col = nt * 8 + lq;
                uint32_t bh0 = __float_as_uint(ws_h[kk + kc][col]);
                uint32_t bh1 = __float_as_uint(ws_h[kk + kc + 4][col]);
                uint32_t bl0 = __float_as_uint(ws_l[kk + kc][col]);
                uint32_t bl1 = __float_as_uint(ws_l[kk + kc + 4][col]);
                mma_tf32(acc[nt], ah, bh0, bh1);   // hi*hi
                mma_tf32(acc[nt], al, bh0, bh1);   // lo*hi
                mma_tf32(acc[nt], ah, bl0, bl1);   // hi*lo
            }
        }
        __syncthreads();
    }

    // epilogue: store raw h (normalization deferred)
    const int gr0 = row0 + wrow + lq;
    const int gr1 = gr0 + 8;
#pragma unroll
    for (int nt = 0; nt < 8; nt++) {
        int col = nt * 8 + kc * 2;
        if (gr0 < n) *(float2*)(g_h + (size_t)gr0 * COUT + col) = make_float2(acc[nt][0], acc[nt][1]);
        if (gr1 < n) *(float2*)(g_h + (size_t)gr1 * COUT + col) = make_float2(acc[nt][2], acc[nt][3]);
    }
}

// ---------------------------------------------------------------------------
// 3) scanA: per-block exclusive scan (warp shuffles) + emit g_dinv
// ---------------------------------------------------------------------------
__global__ void scanA_kernel(int n) {
    __shared__ int wsum[8];
    int i = blockIdx.x * 256 + threadIdx.x;
    int lane = threadIdx.x & 31, wid = threadIdx.x >> 5;
    int v = (i < n) ? g_degi[i] : 0;
    int p = v;
#pragma unroll
    for (int o = 1; o < 32; o <<= 1) {
        int t = __shfl_up_sync(0xffffffffu, p, o);
        if (lane >= o) p += t;
    }
    if (lane == 31) wsum[wid] = p;
    __syncthreads();
    if (wid == 0) {
        int s = (lane < 8) ? wsum[lane] : 0;
#pragma unroll
        for (int o = 1; o < 8; o <<= 1) {
            int t = __shfl_up_sync(0xffffffffu, s, o);
            if (lane >= o) s += t;
        }
        if (lane < 8) wsum[lane] = s;   // inclusive warp sums
    }
    __syncthreads();
    int base = wid ? wsum[wid - 1] : 0;
    if (i < n) {
        g_off[i]  = base + p - v;       // exclusive
        g_dinv[i] = rsqrtf((float)v + 1.0f);
    }
    if (threadIdx.x == 255) g_bsum[blockIdx.x] = base + p;
}

__global__ void scanB_kernel(int nb) {
    __shared__ int s[512];
    int v = (threadIdx.x < nb) ? g_bsum[threadIdx.x] : 0;
    s[threadIdx.x] = v;
    __syncthreads();
#pragma unroll
    for (int off = 1; off < 512; off <<= 1) {
        int t = (threadIdx.x >= off) ? s[threadIdx.x - off] : 0;
        __syncthreads();
        s[threadIdx.x] += t;
        __syncthreads();
    }
    if (threadIdx.x < nb) g_bbase[threadIdx.x] = s[threadIdx.x] - v;
}

__global__ void scanC_kernel(int n) {
    int i = blockIdx.x * 256 + threadIdx.x;
    if (i < n) {
        int o = g_off[i] + g_bbase[blockIdx.x];
        g_off[i] = o;
        g_cur[i] = o;
    }
}

// ---------------------------------------------------------------------------
// 4) FUSED: normalize h (blocks [0,NORM_BLOCKS)) + CSR fill (remaining).
//    norm: g_h[i] *= g_dinv[node]  (h -> h')
//    fill: g_srcl[cur[col]++] = row, 4 edges/thread
// ---------------------------------------------------------------------------
#define NORM_BLOCKS ((NMAX * (COUT / 4) + 255) / 256)   // 6250
__global__ void fill_norm_kernel(const void* __restrict__ ei, int E, int n) {
    if (blockIdx.x < NORM_BLOCKS) {
        int idx = blockIdx.x * 256 + threadIdx.x;        // over N*16 float4s
        if (idx < n * (COUT / 4)) {
            int node = idx >> 4;
            float d = g_dinv[node];
            float4 v = *(float4*)(g_h + (size_t)idx * 4);
            v.x *= d; v.y *= d; v.z *= d; v.w *= d;
            *(float4*)(g_h + (size_t)idx * 4) = v;
        }
    } else {
        int e0 = ((blockIdx.x - NORM_BLOCKS) * 256 + threadIdx.x) * 4;
#pragma unroll
        for (int k = 0; k < 4; k++) {
            int e = e0 + k;
            if (e < E) {
                int r = load_row(ei, e);
                int c = load_col(ei, E, e);
                int pos = atomicAdd(&g_cur[c], 1);
                g_srcl[pos] = r;
            }
        }
    }
}

// ---------------------------------------------------------------------------
// 5) gather + finalize: one warp per node.
//    out[i] = (sum_{s in in(i)} h'[s] + h'[i]) * dinv[i] + b
// ---------------------------------------------------------------------------
__global__ __launch_bounds__(256) void gather_kernel(const float* __restrict__ b,
                                                     float* __restrict__ out, int n) {
    int warp = (blockIdx.x * 256 + threadIdx.x) >> 5;
    int lane = threadIdx.x & 31;
    if (warp >= n) return;

    const int beg = g_off[warp];
    const int d   = g_degi[warp];

    float2 a0 = make_float2(0.f, 0.f);
    float2 a1 = make_float2(0.f, 0.f);
    float2 a2 = make_float2(0.f, 0.f);
    float2 a3 = make_float2(0.f, 0.f);

    for (int j0 = 0; j0 < d; j0 += 32) {
        int m  = min(32, d - j0);
        int sl = (lane < m) ? g_srcl[beg + j0 + lane] : 0;
        int j  = 0;
        for (; j + 3 < m; j += 4) {
            int s0 = __shfl_sync(0xffffffffu, sl, j);
            int s1 = __shfl_sync(0xffffffffu, sl, j + 1);
            int s2 = __shfl_sync(0xffffffffu, sl, j + 2);
            int s3 = __shfl_sync(0xffffffffu, sl, j + 3);
            float2 v0 = *(const float2*)(g_h + (size_t)s0 * COUT + lane * 2);
            float2 v1 = *(const float2*)(g_h + (size_t)s1 * COUT + lane * 2);
            float2 v2 = *(const float2*)(g_h + (size_t)s2 * COUT + lane * 2);
            float2 v3 = *(const float2*)(g_h + (size_t)s3 * COUT + lane * 2);
            a0.x += v0.x; a0.y += v0.y;
            a1.x += v1.x; a1.y += v1.y;
            a2.x += v2.x; a2.y += v2.y;
            a3.x += v3.x; a3.y += v3.y;
        }
        for (; j < m; j++) {
            int s0 = __shfl_sync(0xffffffffu, sl, j);
            float2 v0 = *(const float2*)(g_h + (size_t)s0 * COUT + lane * 2);
            a0.x += v0.x; a0.y += v0.y;
        }
    }

    float2 hs = *(const float2*)(g_h + (size_t)warp * COUT + lane * 2);
    float dinv = g_dinv[warp];
    float2 bb = *(const float2*)(b + lane * 2);
    float2 o;
    o.x = (a0.x + a1.x + a2.x + a3.x + hs.x) * dinv + bb.x;
    o.y = (a0.y + a1.y + a2.y + a3.y + hs.y) * dinv + bb.y;
    *(float2*)(out + (size_t)warp * COUT + lane * 2) = o;
}

// ---------------------------------------------------------------------------
extern "C" void kernel_launch(void* const* d_in, const int* in_sizes, int n_in,
                              void* d_out, int out_size) {
    const float* x  = (const float*)d_in[0];
    const void*  ei = d_in[1];                 // int64 or int32, detected on device
    const float* W  = (const float*)d_in[2];
    const float* b  = (const float*)d_in[3];
    float* out = (float*)d_out;

    const int n = in_sizes[0] / KIN;           // 100000
    const int E = in_sizes[1] / 2;             // 3200000
    const int nblk = (n + 255) / 256;
    const int cnt_blocks  = (E + 1023) / 1024; // 4 edges/thread
    const int fill_blocks = (E + 1023) / 1024;

    detect_zero_kernel<<<nblk + 1, 256>>>((const long long*)ei, n);
    gemm_count_kernel<<<GEMM_BLOCKS + cnt_blocks, 256>>>(x, W, ei, n, E);
    scanA_kernel<<<nblk, 256>>>(n);
    scanB_kernel<<<1, 512>>>(nblk);
    scanC_kernel<<<nblk, 256>>>(n);
    fill_norm_kernel<<<NORM_BLOCKS + fill_blocks, 256>>>(ei, E, n);
    gather_kernel<<<(n * 32 + 255) / 256, 256>>>(b, out, n);
}